// round 16
// baseline (speedup 1.0000x reference)
#include <cuda_runtime.h>
#include <cuda_fp16.h>
#include <math.h>
#include <stdint.h>

// Problem dims (fixed)
#define BB 2
#define TT 2048
#define CC 1024
#define NHH 16
#define HDD 64
#define MTOK 4096          // B*T
#define C3 3072
#define C4 4096

// ---------------- scratch (no allocation allowed) ----------------
__device__ float g_x1 [(size_t)MTOK * CC];
__device__ float g_y  [(size_t)MTOK * CC];

// fp16 weights, transposed to [N][K]
__device__ __half g_wqkv_hi[(size_t)C3 * CC];
__device__ __half g_wa1_hi [(size_t)C4 * CC];
__device__ __half g_wa2_hi [(size_t)CC * C4];
__device__ __half g_wf1_hi [(size_t)C4 * CC];
__device__ __half g_wf2_hi [(size_t)CC * C4];
// fp16 activations
__device__ __half g_ahi [(size_t)MTOK * CC];
__device__ __half g_hhi [(size_t)MTOK * C4];
__device__ __half g_qkvh[(size_t)MTOK * C3];

__device__ __forceinline__ float gelu_f(float v) {
    return 0.5f * v * (1.0f + erff(v * 0.7071067811865475f));
}

// ======================= PTX helpers =======================
__device__ __forceinline__ uint32_t smem_u32(const void* p) {
    uint32_t a;
    asm("{ .reg .u64 t; cvta.to.shared.u64 t, %1; cvt.u32.u64 %0, t; }" : "=r"(a) : "l"(p));
    return a;
}
__device__ __forceinline__ void ldsm4(uint32_t* r, uint32_t addr) {
    asm volatile("ldmatrix.sync.aligned.m8n8.x4.shared.b16 {%0,%1,%2,%3}, [%4];"
                 : "=r"(r[0]), "=r"(r[1]), "=r"(r[2]), "=r"(r[3]) : "r"(addr));
}
__device__ __forceinline__ void ldsm4t(uint32_t* r, uint32_t addr) {
    asm volatile("ldmatrix.sync.aligned.m8n8.x4.trans.shared.b16 {%0,%1,%2,%3}, [%4];"
                 : "=r"(r[0]), "=r"(r[1]), "=r"(r[2]), "=r"(r[3]) : "r"(addr));
}
__device__ __forceinline__ void mma_f16(float* d, const uint32_t* a, const uint32_t* b) {
    asm volatile(
        "mma.sync.aligned.m16n8k16.row.col.f32.f16.f16.f32 "
        "{%0,%1,%2,%3}, {%4,%5,%6,%7}, {%8,%9}, {%0,%1,%2,%3};"
        : "+f"(d[0]), "+f"(d[1]), "+f"(d[2]), "+f"(d[3])
        : "r"(a[0]), "r"(a[1]), "r"(a[2]), "r"(a[3]), "r"(b[0]), "r"(b[1]));
}
__device__ __forceinline__ void cp16(uint32_t dst, const void* src) {
    unsigned long long g = __cvta_generic_to_global(src);
    asm volatile("cp.async.ca.shared.global [%0], [%1], 16;" :: "r"(dst), "l"(g) : "memory");
}
__device__ __forceinline__ void cp_commit() {
    asm volatile("cp.async.commit_group;" ::: "memory");
}
template<int N>
__device__ __forceinline__ void cp_wait() {
    asm volatile("cp.async.wait_group %0;" :: "n"(N) : "memory");
}
__device__ __forceinline__ uint32_t pack2h(float a, float b) {
    __half2 H = __halves2half2(__float2half_rn(a), __float2half_rn(b));
    return *(uint32_t*)&H;
}

// ======================= fused conversion kernel =======================
#define CVT_BLOCKS (19456 + 4096)
__global__ void __launch_bounds__(256)
cvt_all_kernel(const float* __restrict__ W0, __half* __restrict__ h0,
               const float* __restrict__ W1, __half* __restrict__ h1,
               const float* __restrict__ W2, __half* __restrict__ h2,
               const float* __restrict__ W3, __half* __restrict__ h3,
               const float* __restrict__ W4, __half* __restrict__ h4,
               const float* __restrict__ x,  __half* __restrict__ xh)
{
    const int bid = blockIdx.x;
    if (bid >= 19456) {
        int i = ((bid - 19456) * 256 + threadIdx.x) * 4;
        float4 v = *(const float4*)(x + i);
        *(uint32_t*)(xh + i)     = pack2h(v.x, v.y);
        *(uint32_t*)(xh + i + 2) = pack2h(v.z, v.w);
        return;
    }
    __shared__ float tile[32][33];
    const float* W; __half* hi; int K, N, local;
    if      (bid < 3072)  { W = W0; hi = h0; K = CC; N = C3; local = bid; }
    else if (bid < 7168)  { W = W1; hi = h1; K = CC; N = C4; local = bid - 3072; }
    else if (bid < 11264) { W = W2; hi = h2; K = C4; N = CC; local = bid - 7168; }
    else if (bid < 15360) { W = W3; hi = h3; K = CC; N = C4; local = bid - 11264; }
    else                  { W = W4; hi = h4; K = C4; N = CC; local = bid - 15360; }
    const int nb = N >> 5;
    const int n0 = (local % nb) * 32, k0 = (local / nb) * 32;
    const int tx = threadIdx.x & 31, ty = threadIdx.x >> 5;
#pragma unroll
    for (int r = 0; r < 4; ++r)
        tile[ty + r * 8][tx] = W[(size_t)(k0 + ty + r * 8) * N + n0 + tx];
    __syncthreads();
#pragma unroll
    for (int r = 0; r < 4; ++r) {
        int n = n0 + ty + r * 8;
        hi[(size_t)n * K + k0 + tx] = __float2half_rn(tile[tx][ty + r * 8]);
    }
}

// 128B-row swizzle (8 16B units per row, 8-way xor)
__device__ __forceinline__ uint32_t asw(int row, int u) {
    return (uint32_t)(row * 128 + ((u ^ (row & 7)) << 4));
}

// ======================= HMMA fp16 GEMM, CTA 128x128, BK=64, 1-pass ============
// 8 warps (2x4), warp tile 64x32, 2-stage double buffer, 2 CTAs/SM,
// ONE __syncthreads per 64-wide K-chunk; next chunk's cp.async issued AFTER
// the kk=0 fragment loads so the first MMAs are not delayed by the LSU burst.
// MODE 0: fp32 out.  MODE 1: exact-GELU + fp16 hi out.  MODE 2: fp16 hi out.
#define GS1 (2 * 32768)
template<int MODE>
__global__ void __launch_bounds__(256, 2)
gemm_mma_kernel(const __half* __restrict__ Ahi, const __half* __restrict__ Bhi,
                const float* __restrict__ bias, float* __restrict__ Cf,
                __half* __restrict__ Chi, int N, int K)
{
    constexpr uint32_t STAGE = 32768u;

    extern __shared__ char smem[];
    const uint32_t sb = smem_u32(smem);

    const int t = threadIdx.x;
    const int wid = t >> 5, lane = t & 31;
    const int bm = blockIdx.y * 128;
    const int bn = blockIdx.x * 128;
    const int wm = wid >> 2, wn = wid & 3;

    float acc[4][4][4];
#pragma unroll
    for (int i = 0; i < 4; ++i)
#pragma unroll
        for (int j = 0; j < 4; ++j)
#pragma unroll
            for (int k = 0; k < 4; ++k) acc[i][j][k] = 0.0f;

    const int nc = K >> 6;

    const int g  = lane >> 3, lr = lane & 7;
    const int a_rit = lr + (g & 1) * 8, a_kqo = g >> 1;
    const int b_rit = lr + (g >> 1) * 8, b_kqo = g & 1;

    uint32_t aA[4], aBh[2];
    int aRsw[4], bRsw[2];
#pragma unroll
    for (int mt = 0; mt < 4; ++mt) {
        int row = wm * 64 + mt * 16 + a_rit;
        aA[mt] = sb + row * 128;
        aRsw[mt] = row & 7;
    }
#pragma unroll
    for (int p = 0; p < 2; ++p) {
        int row = wn * 32 + p * 16 + b_rit;
        aBh[p] = sb + 16384u + row * 128;
        bRsw[p] = row & 7;
    }

    auto issue = [&](int c, int s) {
        const uint32_t st = sb + s * STAGE;
        const int kb = c * 64;
#pragma unroll
        for (int i = 0; i < 8; ++i) {
            int u = t + i * 256;
            int arr = u >> 10, v = u & 1023, row = v >> 3, kq = v & 7;
            const __half* src = (arr ? Bhi : Ahi) +
                (size_t)((arr ? bn : bm) + row) * K + kb + kq * 8;
            cp16(st + arr * 16384u + asw(row, kq), src);
        }
        cp_commit();
    };

    // fragment loader for one kk step
    auto load_frags = [&](uint32_t stoff, int kk, uint32_t ah[4][4], uint32_t bh[4][2]) {
#pragma unroll
        for (int mt = 0; mt < 4; ++mt) {
            uint32_t o = (uint32_t)(((((kk << 1) | a_kqo) ^ aRsw[mt]) << 4));
            ldsm4(ah[mt], aA[mt] + stoff + o);
        }
#pragma unroll
        for (int p = 0; p < 2; ++p) {
            uint32_t r[4];
            uint32_t o = (uint32_t)(((((kk << 1) | b_kqo) ^ bRsw[p]) << 4));
            ldsm4(r, aBh[p] + stoff + o);
            bh[2 * p][0] = r[0]; bh[2 * p][1] = r[1];
            bh[2 * p + 1][0] = r[2]; bh[2 * p + 1][1] = r[3];
        }
    };

    issue(0, 0);
    int s = 0;
    for (int c = 0; c < nc; ++c) {
        cp_wait<0>();
        __syncthreads();

        const uint32_t stoff = (uint32_t)(s * STAGE);
        // kk = 0: fragments first, then the next chunk's cp.async burst
        {
            uint32_t ah[4][4], bh[4][2];
            load_frags(stoff, 0, ah, bh);
            if (c + 1 < nc) issue(c + 1, s ^ 1);
#pragma unroll
            for (int mt = 0; mt < 4; ++mt)
#pragma unroll
                for (int nt = 0; nt < 4; ++nt)
                    mma_f16(acc[mt][nt], ah[mt], bh[nt]);
        }
#pragma unroll
        for (int kk = 1; kk < 4; ++kk) {
            uint32_t ah[4][4], bh[4][2];
            load_frags(stoff, kk, ah, bh);
#pragma unroll
            for (int mt = 0; mt < 4; ++mt)
#pragma unroll
                for (int nt = 0; nt < 4; ++nt)
                    mma_f16(acc[mt][nt], ah[mt], bh[nt]);
        }
        s ^= 1;
    }

    const int mrow = bm + wm * 64;
    const int ncol = bn + wn * 32;
#pragma unroll
    for (int mt = 0; mt < 4; ++mt) {
#pragma unroll
        for (int nt = 0; nt < 4; ++nt) {
            float* d = acc[mt][nt];
            int r0 = mrow + mt * 16 + (lane >> 2);
            int cix = ncol + nt * 8 + (lane & 3) * 2;
            float b0 = bias[cix], b1 = bias[cix + 1];
            float v00 = d[0] + b0, v01 = d[1] + b1;
            float v10 = d[2] + b0, v11 = d[3] + b1;
            if (MODE == 0) {
                float2 p0{v00, v01}, p1{v10, v11};
                *(float2*)&Cf[(size_t)r0 * N + cix]       = p0;
                *(float2*)&Cf[(size_t)(r0 + 8) * N + cix] = p1;
            } else {
                if (MODE == 1) {
                    v00 = gelu_f(v00); v01 = gelu_f(v01);
                    v10 = gelu_f(v10); v11 = gelu_f(v11);
                }
                *(uint32_t*)&Chi[(size_t)r0 * N + cix]       = pack2h(v00, v01);
                *(uint32_t*)&Chi[(size_t)(r0 + 8) * N + cix] = pack2h(v10, v11);
            }
        }
    }
}

// ======================= HMMA causal attention =======================
// 128 threads, Q tile 64 rows, 3 CTAs/SM. QK 1-pass, PV 1-pass.
// smem: Qh 8K | Kh 8K | Vh 8K = 24KB.
#define ASMEM 24576

__global__ void __launch_bounds__(128, 3)
attn_mma_kernel(const __half* __restrict__ qkvh, __half* __restrict__ ohi)
{
    extern __shared__ char asmem[];
    const uint32_t sb = smem_u32(asmem);

    const int t = threadIdx.x, wid = t >> 5, lane = t & 31;
    const int qi = gridDim.x - 1 - blockIdx.x;
    const int qb = qi * 64;
    const int h  = blockIdx.y, b = blockIdx.z;

    const __half* Kh_g = qkvh + (size_t)b * TT * C3 + h * HDD;
    const __half* Qh_g = Kh_g + CC;
    const __half* Vh_g = Kh_g + 2 * CC;

#pragma unroll
    for (int i = 0; i < 4; ++i) {
        int uu = t + i * 128;
        int row = uu >> 3, u = uu & 7;
        cp16(sb + asw(row, u), Qh_g + (size_t)(qb + row) * C3 + u * 8);
    }
    cp_commit();

    const int g = lane >> 3, lr = lane & 7;
    const int r = lane >> 2, c = lane & 3;
    const int qrow = wid * 16 + lr + ((g & 1) << 3);
    const int a_u  = g >> 1;
    const int krit = lr + ((g >> 1) << 3);
    const int b_u  = g & 1;
    const int vrit = lr + ((g & 1) << 3);
    const int v_u  = g >> 1;

    float O[8][4];
#pragma unroll
    for (int i = 0; i < 8; ++i)
#pragma unroll
        for (int j = 0; j < 4; ++j) O[i][j] = 0.0f;
    float m0 = -1e30f, m1 = -1e30f, l0 = 0.0f, l1 = 0.0f;

    const int ntiles = qi + 1;
    for (int kt = 0; kt < ntiles; ++kt) {
        const int kb = kt * 64;
        __syncthreads();
#pragma unroll
        for (int i = 0; i < 8; ++i) {
            int uu = t + i * 128;
            int arr = uu >> 9, v = uu & 511, row = v >> 3, u = v & 7;
            const __half* src = (arr ? Vh_g : Kh_g) + (size_t)(kb + row) * C3 + u * 8;
            cp16(sb + 8192 + arr * 8192 + asw(row, u), src);
        }
        cp_commit();
        cp_wait<0>();
        __syncthreads();

        float S[8][4];
#pragma unroll
        for (int i = 0; i < 8; ++i)
#pragma unroll
            for (int j = 0; j < 4; ++j) S[i][j] = 0.0f;

#pragma unroll
        for (int kk = 0; kk < 4; ++kk) {
            uint32_t ah[4];
            uint32_t aoq = (uint32_t)(qrow * 128 + ((((kk << 1) | a_u) ^ (qrow & 7)) << 4));
            ldsm4(ah, sb + aoq);
#pragma unroll
            for (int p = 0; p < 4; ++p) {
                int krow = (p << 4) + krit;
                uint32_t ko = (uint32_t)(krow * 128 + ((((kk << 1) | b_u) ^ (krow & 7)) << 4));
                uint32_t bh[4];
                ldsm4(bh, sb + 8192 + ko);
                mma_f16(S[2 * p],     ah, bh);
                mma_f16(S[2 * p + 1], ah, bh + 2);
            }
        }

#pragma unroll
        for (int nt = 0; nt < 8; ++nt)
#pragma unroll
            for (int e = 0; e < 4; ++e) S[nt][e] *= 0.125f;
        if (kt == qi) {
            const int q0 = qb + wid * 16 + r, q1 = q0 + 8;
#pragma unroll
            for (int nt = 0; nt < 8; ++nt) {
                int k0 = kb + 8 * nt + 2 * c;
                if (k0     > q0) S[nt][0] = -1e30f;
                if (k0 + 1 > q0) S[nt][1] = -1e30f;
                if (k0     > q1) S[nt][2] = -1e30f;
                if (k0 + 1 > q1) S[nt][3] = -1e30f;
            }
        }

        float mx0 = -1e30f, mx1 = -1e30f;
#pragma unroll
        for (int nt = 0; nt < 8; ++nt) {
            mx0 = fmaxf(mx0, fmaxf(S[nt][0], S[nt][1]));
            mx1 = fmaxf(mx1, fmaxf(S[nt][2], S[nt][3]));
        }
        mx0 = fmaxf(mx0, __shfl_xor_sync(0xffffffffu, mx0, 1));
        mx0 = fmaxf(mx0, __shfl_xor_sync(0xffffffffu, mx0, 2));
        mx1 = fmaxf(mx1, __shfl_xor_sync(0xffffffffu, mx1, 1));
        mx1 = fmaxf(mx1, __shfl_xor_sync(0xffffffffu, mx1, 2));
        float mn0 = fmaxf(m0, mx0), mn1 = fmaxf(m1, mx1);
        float al0 = __expf(m0 - mn0), al1 = __expf(m1 - mn1);
        m0 = mn0; m1 = mn1;

        float s0 = 0.0f, s1 = 0.0f;
#pragma unroll
        for (int nt = 0; nt < 8; ++nt) {
            S[nt][0] = __expf(S[nt][0] - mn0);
            S[nt][1] = __expf(S[nt][1] - mn0);
            S[nt][2] = __expf(S[nt][2] - mn1);
            S[nt][3] = __expf(S[nt][3] - mn1);
            s0 += S[nt][0] + S[nt][1];
            s1 += S[nt][2] + S[nt][3];
        }
        l0 = l0 * al0 + s0;
        l1 = l1 * al1 + s1;
#pragma unroll
        for (int nt = 0; nt < 8; ++nt) {
            O[nt][0] *= al0; O[nt][1] *= al0;
            O[nt][2] *= al1; O[nt][3] *= al1;
        }

#pragma unroll
        for (int kk = 0; kk < 4; ++kk) {
            uint32_t ph[4];
            ph[0] = pack2h(S[2 * kk][0],     S[2 * kk][1]);
            ph[1] = pack2h(S[2 * kk][2],     S[2 * kk][3]);
            ph[2] = pack2h(S[2 * kk + 1][0], S[2 * kk + 1][1]);
            ph[3] = pack2h(S[2 * kk + 1][2], S[2 * kk + 1][3]);
            int vrow = (kk << 4) + vrit;
#pragma unroll
            for (int p = 0; p < 4; ++p) {
                uint32_t vo = (uint32_t)(vrow * 128 + ((((p << 1) | v_u) ^ (vrow & 7)) << 4));
                uint32_t vh[4];
                ldsm4t(vh, sb + 16384 + vo);
                mma_f16(O[2 * p],     ph, vh);
                mma_f16(O[2 * p + 1], ph, vh + 2);
            }
        }
    }

    l0 += __shfl_xor_sync(0xffffffffu, l0, 1);
    l0 += __shfl_xor_sync(0xffffffffu, l0, 2);
    l1 += __shfl_xor_sync(0xffffffffu, l1, 1);
    l1 += __shfl_xor_sync(0xffffffffu, l1, 2);
    const float i0 = 1.0f / l0, i1 = 1.0f / l1;
    const int row0 = qb + wid * 16 + r, row1 = row0 + 8;
#pragma unroll
    for (int nt = 0; nt < 8; ++nt) {
        int col = h * HDD + 8 * nt + 2 * c;
        size_t idx0 = ((size_t)b * TT + row0) * CC + col;
        size_t idx1 = ((size_t)b * TT + row1) * CC + col;
        *(uint32_t*)&ohi[idx0] = pack2h(O[nt][0] * i0, O[nt][1] * i0);
        *(uint32_t*)&ohi[idx1] = pack2h(O[nt][2] * i1, O[nt][3] * i1);
    }
}

// ---------------- LayerNorm + residual ----------------
__device__ __forceinline__ float block_sum(float v, float* red) {
    const int lane = threadIdx.x & 31, w = threadIdx.x >> 5;
#pragma unroll
    for (int o = 16; o; o >>= 1) v += __shfl_xor_sync(0xffffffffu, v, o);
    if (lane == 0) red[w] = v;
    __syncthreads();
    if (w == 0) {
        float s = (lane < 8) ? red[lane] : 0.0f;
#pragma unroll
        for (int o = 4; o; o >>= 1) s += __shfl_xor_sync(0xffffffffu, s, o);
        if (lane == 0) red[0] = s;
    }
    __syncthreads();
    float rr = red[0];
    __syncthreads();
    return rr;
}

template<bool SPLIT>
__global__ void __launch_bounds__(256)
ln_res_kernel(const float* __restrict__ res, const float* __restrict__ y,
              const float* __restrict__ g, const float* __restrict__ be,
              float* __restrict__ out, __half* __restrict__ ohi)
{
    __shared__ float red[8];
    const int row = blockIdx.x;
    const int t = threadIdx.x;
    const float* yr = y + (size_t)row * CC;

    float v[4];
    float s = 0.0f;
#pragma unroll
    for (int i = 0; i < 4; ++i) { v[i] = yr[t + i * 256]; s += v[i]; }
    const float mean = block_sum(s, red) * (1.0f / CC);

    float sq = 0.0f;
#pragma unroll
    for (int i = 0; i < 4; ++i) { float d = v[i] - mean; sq += d * d; }
    const float var = block_sum(sq, red) * (1.0f / CC);
    const float rstd = rsqrtf(var + 1e-5f);

    const float* rr = res + (size_t)row * CC;
    float* orow = out + (size_t)row * CC;
#pragma unroll
    for (int i = 0; i < 4; ++i) {
        int cix = t + i * 256;
        float o = rr[cix] + (v[i] - mean) * rstd * g[cix] + be[cix];
        orow[cix] = o;
        if (SPLIT) ohi[(size_t)row * CC + cix] = __float2half_rn(o);
    }
}

// ---------------- launch ----------------
extern "C" void kernel_launch(void* const* d_in, const int* in_sizes, int n_in,
                              void* d_out, int out_size)
{
    const float* x      = (const float*)d_in[0];
    const float* w_attn = (const float*)d_in[1];
    const float* b_attn = (const float*)d_in[2];
    const float* wa1    = (const float*)d_in[3];
    const float* ba1    = (const float*)d_in[4];
    const float* wa2    = (const float*)d_in[5];
    const float* ba2    = (const float*)d_in[6];
    const float* g1     = (const float*)d_in[7];
    const float* be1    = (const float*)d_in[8];
    const float* wf1    = (const float*)d_in[9];
    const float* bf1    = (const float*)d_in[10];
    const float* wf2    = (const float*)d_in[11];
    const float* bf2    = (const float*)d_in[12];
    const float* g2     = (const float*)d_in[13];
    const float* be2    = (const float*)d_in[14];
    float* out = (float*)d_out;

    float *x1, *y;
    cudaGetSymbolAddress((void**)&x1, g_x1);
    cudaGetSymbolAddress((void**)&y,  g_y);

    __half *wqkv_hi, *wa1_hi, *wa2_hi, *wf1_hi, *wf2_hi, *ahi, *hhi, *qkvh;
    cudaGetSymbolAddress((void**)&wqkv_hi, g_wqkv_hi);
    cudaGetSymbolAddress((void**)&wa1_hi,  g_wa1_hi);
    cudaGetSymbolAddress((void**)&wa2_hi,  g_wa2_hi);
    cudaGetSymbolAddress((void**)&wf1_hi,  g_wf1_hi);
    cudaGetSymbolAddress((void**)&wf2_hi,  g_wf2_hi);
    cudaGetSymbolAddress((void**)&ahi,     g_ahi);
    cudaGetSymbolAddress((void**)&hhi,     g_hhi);
    cudaGetSymbolAddress((void**)&qkvh,    g_qkvh);

    cudaFuncSetAttribute(attn_mma_kernel, cudaFuncAttributeMaxDynamicSharedMemorySize, ASMEM);
    cudaFuncSetAttribute(gemm_mma_kernel<0>, cudaFuncAttributeMaxDynamicSharedMemorySize, GS1);
    cudaFuncSetAttribute(gemm_mma_kernel<1>, cudaFuncAttributeMaxDynamicSharedMemorySize, GS1);
    cudaFuncSetAttribute(gemm_mma_kernel<2>, cudaFuncAttributeMaxDynamicSharedMemorySize, GS1);

    // all conversions (5 weights + x) in one launch
    cvt_all_kernel<<<CVT_BLOCKS, 256>>>(
        w_attn, wqkv_hi,
        wa1, wa1_hi,
        wa2, wa2_hi,
        wf1, wf1_hi,
        wf2, wf2_hi,
        x, ahi);

    // 1) qkv = x @ w_attn + b_attn
    gemm_mma_kernel<2><<<dim3(C3 / 128, MTOK / 128), 256, GS1>>>(
        ahi, wqkv_hi, b_attn, nullptr, qkvh, C3, CC);
    // 2) attention
    attn_mma_kernel<<<dim3(TT / 64, NHH, BB), 128, ASMEM>>>(qkvh, ahi);
    // 3) h = gelu(att @ wa1 + ba1)
    gemm_mma_kernel<1><<<dim3(C4 / 128, MTOK / 128), 256, GS1>>>(
        ahi, wa1_hi, ba1, nullptr, hhi, C4, CC);
    // 4) y = h @ wa2 + ba2
    gemm_mma_kernel<0><<<dim3(CC / 128, MTOK / 128), 256, GS1>>>(
        hhi, wa2_hi, ba2, y, nullptr, CC, C4);
    // 5) x1 = x + ln(y); emit fp16 x1
    ln_res_kernel<true><<<MTOK, 256>>>(x, y, g1, be1, x1, ahi);
    // 6) h = gelu(x1 @ wf1 + bf1)
    gemm_mma_kernel<1><<<dim3(C4 / 128, MTOK / 128), 256, GS1>>>(
        ahi, wf1_hi, bf1, nullptr, hhi, C4, CC);
    // 7) y = h @ wf2 + bf2
    gemm_mma_kernel<0><<<dim3(CC / 128, MTOK / 128), 256, GS1>>>(
        hhi, wf2_hi, bf2, y, nullptr, CC, C4);
    // 8) out = x1 + ln(y)
    ln_res_kernel<false><<<MTOK, 256>>>(x1, y, g2, be2, out, nullptr);
}

// round 17
// speedup vs baseline: 1.1558x; 1.1558x over previous
#include <cuda_runtime.h>
#include <cuda_fp16.h>
#include <math.h>
#include <stdint.h>

// Problem dims (fixed)
#define BB 2
#define TT 2048
#define CC 1024
#define NHH 16
#define HDD 64
#define MTOK 4096          // B*T
#define C3 3072
#define C4 4096

// ---------------- scratch (no allocation allowed) ----------------
__device__ float g_x1 [(size_t)MTOK * CC];
__device__ float g_y  [(size_t)MTOK * CC];

// fp16 weights, transposed to [N][K]
__device__ __half g_wqkv_hi[(size_t)C3 * CC];
__device__ __half g_wa1_hi [(size_t)C4 * CC];
__device__ __half g_wa2_hi [(size_t)CC * C4];
__device__ __half g_wf1_hi [(size_t)C4 * CC];
__device__ __half g_wf2_hi [(size_t)CC * C4];
// fp16 activations
__device__ __half g_ahi [(size_t)MTOK * CC];
__device__ __half g_hhi [(size_t)MTOK * C4];
__device__ __half g_qkvh[(size_t)MTOK * C3];

__device__ __forceinline__ float gelu_f(float v) {
    return 0.5f * v * (1.0f + erff(v * 0.7071067811865475f));
}

// ======================= PTX helpers =======================
__device__ __forceinline__ uint32_t smem_u32(const void* p) {
    uint32_t a;
    asm("{ .reg .u64 t; cvta.to.shared.u64 t, %1; cvt.u32.u64 %0, t; }" : "=r"(a) : "l"(p));
    return a;
}
__device__ __forceinline__ void ldsm4(uint32_t* r, uint32_t addr) {
    asm volatile("ldmatrix.sync.aligned.m8n8.x4.shared.b16 {%0,%1,%2,%3}, [%4];"
                 : "=r"(r[0]), "=r"(r[1]), "=r"(r[2]), "=r"(r[3]) : "r"(addr));
}
__device__ __forceinline__ void ldsm4t(uint32_t* r, uint32_t addr) {
    asm volatile("ldmatrix.sync.aligned.m8n8.x4.trans.shared.b16 {%0,%1,%2,%3}, [%4];"
                 : "=r"(r[0]), "=r"(r[1]), "=r"(r[2]), "=r"(r[3]) : "r"(addr));
}
__device__ __forceinline__ void mma_f16(float* d, const uint32_t* a, const uint32_t* b) {
    asm volatile(
        "mma.sync.aligned.m16n8k16.row.col.f32.f16.f16.f32 "
        "{%0,%1,%2,%3}, {%4,%5,%6,%7}, {%8,%9}, {%0,%1,%2,%3};"
        : "+f"(d[0]), "+f"(d[1]), "+f"(d[2]), "+f"(d[3])
        : "r"(a[0]), "r"(a[1]), "r"(a[2]), "r"(a[3]), "r"(b[0]), "r"(b[1]));
}
// L2-only (no L1 allocation) bulk copy — operands are streamed, not reused via L1.
__device__ __forceinline__ void cp16(uint32_t dst, const void* src) {
    unsigned long long g = __cvta_generic_to_global(src);
    asm volatile("cp.async.cg.shared.global [%0], [%1], 16;" :: "r"(dst), "l"(g) : "memory");
}
__device__ __forceinline__ void cp_commit() {
    asm volatile("cp.async.commit_group;" ::: "memory");
}
template<int N>
__device__ __forceinline__ void cp_wait() {
    asm volatile("cp.async.wait_group %0;" :: "n"(N) : "memory");
}
__device__ __forceinline__ uint32_t pack2h(float a, float b) {
    __half2 H = __halves2half2(__float2half_rn(a), __float2half_rn(b));
    return *(uint32_t*)&H;
}

// ======================= fused conversion kernel =======================
#define CVT_BLOCKS (19456 + 4096)
__global__ void __launch_bounds__(256)
cvt_all_kernel(const float* __restrict__ W0, __half* __restrict__ h0,
               const float* __restrict__ W1, __half* __restrict__ h1,
               const float* __restrict__ W2, __half* __restrict__ h2,
               const float* __restrict__ W3, __half* __restrict__ h3,
               const float* __restrict__ W4, __half* __restrict__ h4,
               const float* __restrict__ x,  __half* __restrict__ xh)
{
    const int bid = blockIdx.x;
    if (bid >= 19456) {
        int i = ((bid - 19456) * 256 + threadIdx.x) * 4;
        float4 v = *(const float4*)(x + i);
        *(uint32_t*)(xh + i)     = pack2h(v.x, v.y);
        *(uint32_t*)(xh + i + 2) = pack2h(v.z, v.w);
        return;
    }
    __shared__ float tile[32][33];
    const float* W; __half* hi; int K, N, local;
    if      (bid < 3072)  { W = W0; hi = h0; K = CC; N = C3; local = bid; }
    else if (bid < 7168)  { W = W1; hi = h1; K = CC; N = C4; local = bid - 3072; }
    else if (bid < 11264) { W = W2; hi = h2; K = C4; N = CC; local = bid - 7168; }
    else if (bid < 15360) { W = W3; hi = h3; K = CC; N = C4; local = bid - 11264; }
    else                  { W = W4; hi = h4; K = C4; N = CC; local = bid - 15360; }
    const int nb = N >> 5;
    const int n0 = (local % nb) * 32, k0 = (local / nb) * 32;
    const int tx = threadIdx.x & 31, ty = threadIdx.x >> 5;
#pragma unroll
    for (int r = 0; r < 4; ++r)
        tile[ty + r * 8][tx] = W[(size_t)(k0 + ty + r * 8) * N + n0 + tx];
    __syncthreads();
#pragma unroll
    for (int r = 0; r < 4; ++r) {
        int n = n0 + ty + r * 8;
        hi[(size_t)n * K + k0 + tx] = __float2half_rn(tile[tx][ty + r * 8]);
    }
}

// 128B-row swizzle (8 16B units per row, 8-way xor)
__device__ __forceinline__ uint32_t asw(int row, int u) {
    return (uint32_t)(row * 128 + ((u ^ (row & 7)) << 4));
}

// ======================= HMMA fp16 GEMM, CTA 128x128, BK=64, 1-pass ============
// 8 warps (2x4), warp tile 64x32, 2-stage double buffer, 2 CTAs/SM,
// ONE __syncthreads per 64-wide K-chunk (R14-proven schedule).
// MODE 0: fp32 out.  MODE 1: exact-GELU + fp16 hi out.  MODE 2: fp16 hi out.
#define GS1 (2 * 32768)
template<int MODE>
__global__ void __launch_bounds__(256, 2)
gemm_mma_kernel(const __half* __restrict__ Ahi, const __half* __restrict__ Bhi,
                const float* __restrict__ bias, float* __restrict__ Cf,
                __half* __restrict__ Chi, int N, int K)
{
    constexpr uint32_t STAGE = 32768u;

    extern __shared__ char smem[];
    const uint32_t sb = smem_u32(smem);

    const int t = threadIdx.x;
    const int wid = t >> 5, lane = t & 31;
    const int bm = blockIdx.y * 128;
    const int bn = blockIdx.x * 128;
    const int wm = wid >> 2, wn = wid & 3;

    float acc[4][4][4];
#pragma unroll
    for (int i = 0; i < 4; ++i)
#pragma unroll
        for (int j = 0; j < 4; ++j)
#pragma unroll
            for (int k = 0; k < 4; ++k) acc[i][j][k] = 0.0f;

    const int nc = K >> 6;

    const int g  = lane >> 3, lr = lane & 7;
    const int a_rit = lr + (g & 1) * 8, a_kqo = g >> 1;
    const int b_rit = lr + (g >> 1) * 8, b_kqo = g & 1;

    uint32_t aA[4], aBh[2];
    int aRsw[4], bRsw[2];
#pragma unroll
    for (int mt = 0; mt < 4; ++mt) {
        int row = wm * 64 + mt * 16 + a_rit;
        aA[mt] = sb + row * 128;
        aRsw[mt] = row & 7;
    }
#pragma unroll
    for (int p = 0; p < 2; ++p) {
        int row = wn * 32 + p * 16 + b_rit;
        aBh[p] = sb + 16384u + row * 128;
        bRsw[p] = row & 7;
    }

    auto issue = [&](int c, int s) {
        const uint32_t st = sb + s * STAGE;
        const int kb = c * 64;
#pragma unroll
        for (int i = 0; i < 8; ++i) {
            int u = t + i * 256;
            int arr = u >> 10, v = u & 1023, row = v >> 3, kq = v & 7;
            const __half* src = (arr ? Bhi : Ahi) +
                (size_t)((arr ? bn : bm) + row) * K + kb + kq * 8;
            cp16(st + arr * 16384u + asw(row, kq), src);
        }
        cp_commit();
    };

    issue(0, 0);
    int s = 0;
    for (int c = 0; c < nc; ++c) {
        cp_wait<0>();
        __syncthreads();
        if (c + 1 < nc) issue(c + 1, s ^ 1);

        const uint32_t stoff = (uint32_t)(s * STAGE);
#pragma unroll
        for (int kk = 0; kk < 4; ++kk) {
            uint32_t ah[4][4], bh[4][2];
#pragma unroll
            for (int mt = 0; mt < 4; ++mt) {
                uint32_t o = (uint32_t)(((((kk << 1) | a_kqo) ^ aRsw[mt]) << 4));
                ldsm4(ah[mt], aA[mt] + stoff + o);
            }
#pragma unroll
            for (int p = 0; p < 2; ++p) {
                uint32_t r[4];
                uint32_t o = (uint32_t)(((((kk << 1) | b_kqo) ^ bRsw[p]) << 4));
                ldsm4(r, aBh[p] + stoff + o);
                bh[2 * p][0] = r[0]; bh[2 * p][1] = r[1];
                bh[2 * p + 1][0] = r[2]; bh[2 * p + 1][1] = r[3];
            }
#pragma unroll
            for (int mt = 0; mt < 4; ++mt)
#pragma unroll
                for (int nt = 0; nt < 4; ++nt)
                    mma_f16(acc[mt][nt], ah[mt], bh[nt]);
        }
        s ^= 1;
    }

    const int mrow = bm + wm * 64;
    const int ncol = bn + wn * 32;
#pragma unroll
    for (int mt = 0; mt < 4; ++mt) {
#pragma unroll
        for (int nt = 0; nt < 4; ++nt) {
            float* d = acc[mt][nt];
            int r0 = mrow + mt * 16 + (lane >> 2);
            int cix = ncol + nt * 8 + (lane & 3) * 2;
            float b0 = bias[cix], b1 = bias[cix + 1];
            float v00 = d[0] + b0, v01 = d[1] + b1;
            float v10 = d[2] + b0, v11 = d[3] + b1;
            if (MODE == 0) {
                float2 p0{v00, v01}, p1{v10, v11};
                *(float2*)&Cf[(size_t)r0 * N + cix]       = p0;
                *(float2*)&Cf[(size_t)(r0 + 8) * N + cix] = p1;
            } else {
                if (MODE == 1) {
                    v00 = gelu_f(v00); v01 = gelu_f(v01);
                    v10 = gelu_f(v10); v11 = gelu_f(v11);
                }
                *(uint32_t*)&Chi[(size_t)r0 * N + cix]       = pack2h(v00, v01);
                *(uint32_t*)&Chi[(size_t)(r0 + 8) * N + cix] = pack2h(v10, v11);
            }
        }
    }
}

// ======================= HMMA causal attention =======================
// 128 threads, Q tile 64 rows, 3 CTAs/SM. QK 1-pass, PV 1-pass.
// smem: Qh 8K | Kh 8K | Vh 8K = 24KB.
#define ASMEM 24576

__global__ void __launch_bounds__(128, 3)
attn_mma_kernel(const __half* __restrict__ qkvh, __half* __restrict__ ohi)
{
    extern __shared__ char asmem[];
    const uint32_t sb = smem_u32(asmem);

    const int t = threadIdx.x, wid = t >> 5, lane = t & 31;
    const int qi = gridDim.x - 1 - blockIdx.x;
    const int qb = qi * 64;
    const int h  = blockIdx.y, b = blockIdx.z;

    const __half* Kh_g = qkvh + (size_t)b * TT * C3 + h * HDD;
    const __half* Qh_g = Kh_g + CC;
    const __half* Vh_g = Kh_g + 2 * CC;

#pragma unroll
    for (int i = 0; i < 4; ++i) {
        int uu = t + i * 128;
        int row = uu >> 3, u = uu & 7;
        cp16(sb + asw(row, u), Qh_g + (size_t)(qb + row) * C3 + u * 8);
    }
    cp_commit();

    const int g = lane >> 3, lr = lane & 7;
    const int r = lane >> 2, c = lane & 3;
    const int qrow = wid * 16 + lr + ((g & 1) << 3);
    const int a_u  = g >> 1;
    const int krit = lr + ((g >> 1) << 3);
    const int b_u  = g & 1;
    const int vrit = lr + ((g & 1) << 3);
    const int v_u  = g >> 1;

    float O[8][4];
#pragma unroll
    for (int i = 0; i < 8; ++i)
#pragma unroll
        for (int j = 0; j < 4; ++j) O[i][j] = 0.0f;
    float m0 = -1e30f, m1 = -1e30f, l0 = 0.0f, l1 = 0.0f;

    const int ntiles = qi + 1;
    for (int kt = 0; kt < ntiles; ++kt) {
        const int kb = kt * 64;
        __syncthreads();
#pragma unroll
        for (int i = 0; i < 8; ++i) {
            int uu = t + i * 128;
            int arr = uu >> 9, v = uu & 511, row = v >> 3, u = v & 7;
            const __half* src = (arr ? Vh_g : Kh_g) + (size_t)(kb + row) * C3 + u * 8;
            cp16(sb + 8192 + arr * 8192 + asw(row, u), src);
        }
        cp_commit();
        cp_wait<0>();
        __syncthreads();

        float S[8][4];
#pragma unroll
        for (int i = 0; i < 8; ++i)
#pragma unroll
            for (int j = 0; j < 4; ++j) S[i][j] = 0.0f;

#pragma unroll
        for (int kk = 0; kk < 4; ++kk) {
            uint32_t ah[4];
            uint32_t aoq = (uint32_t)(qrow * 128 + ((((kk << 1) | a_u) ^ (qrow & 7)) << 4));
            ldsm4(ah, sb + aoq);
#pragma unroll
            for (int p = 0; p < 4; ++p) {
                int krow = (p << 4) + krit;
                uint32_t ko = (uint32_t)(krow * 128 + ((((kk << 1) | b_u) ^ (krow & 7)) << 4));
                uint32_t bh[4];
                ldsm4(bh, sb + 8192 + ko);
                mma_f16(S[2 * p],     ah, bh);
                mma_f16(S[2 * p + 1], ah, bh + 2);
            }
        }

#pragma unroll
        for (int nt = 0; nt < 8; ++nt)
#pragma unroll
            for (int e = 0; e < 4; ++e) S[nt][e] *= 0.125f;
        if (kt == qi) {
            const int q0 = qb + wid * 16 + r, q1 = q0 + 8;
#pragma unroll
            for (int nt = 0; nt < 8; ++nt) {
                int k0 = kb + 8 * nt + 2 * c;
                if (k0     > q0) S[nt][0] = -1e30f;
                if (k0 + 1 > q0) S[nt][1] = -1e30f;
                if (k0     > q1) S[nt][2] = -1e30f;
                if (k0 + 1 > q1) S[nt][3] = -1e30f;
            }
        }

        float mx0 = -1e30f, mx1 = -1e30f;
#pragma unroll
        for (int nt = 0; nt < 8; ++nt) {
            mx0 = fmaxf(mx0, fmaxf(S[nt][0], S[nt][1]));
            mx1 = fmaxf(mx1, fmaxf(S[nt][2], S[nt][3]));
        }
        mx0 = fmaxf(mx0, __shfl_xor_sync(0xffffffffu, mx0, 1));
        mx0 = fmaxf(mx0, __shfl_xor_sync(0xffffffffu, mx0, 2));
        mx1 = fmaxf(mx1, __shfl_xor_sync(0xffffffffu, mx1, 1));
        mx1 = fmaxf(mx1, __shfl_xor_sync(0xffffffffu, mx1, 2));
        float mn0 = fmaxf(m0, mx0), mn1 = fmaxf(m1, mx1);
        float al0 = __expf(m0 - mn0), al1 = __expf(m1 - mn1);
        m0 = mn0; m1 = mn1;

        float s0 = 0.0f, s1 = 0.0f;
#pragma unroll
        for (int nt = 0; nt < 8; ++nt) {
            S[nt][0] = __expf(S[nt][0] - mn0);
            S[nt][1] = __expf(S[nt][1] - mn0);
            S[nt][2] = __expf(S[nt][2] - mn1);
            S[nt][3] = __expf(S[nt][3] - mn1);
            s0 += S[nt][0] + S[nt][1];
            s1 += S[nt][2] + S[nt][3];
        }
        l0 = l0 * al0 + s0;
        l1 = l1 * al1 + s1;
#pragma unroll
        for (int nt = 0; nt < 8; ++nt) {
            O[nt][0] *= al0; O[nt][1] *= al0;
            O[nt][2] *= al1; O[nt][3] *= al1;
        }

#pragma unroll
        for (int kk = 0; kk < 4; ++kk) {
            uint32_t ph[4];
            ph[0] = pack2h(S[2 * kk][0],     S[2 * kk][1]);
            ph[1] = pack2h(S[2 * kk][2],     S[2 * kk][3]);
            ph[2] = pack2h(S[2 * kk + 1][0], S[2 * kk + 1][1]);
            ph[3] = pack2h(S[2 * kk + 1][2], S[2 * kk + 1][3]);
            int vrow = (kk << 4) + vrit;
#pragma unroll
            for (int p = 0; p < 4; ++p) {
                uint32_t vo = (uint32_t)(vrow * 128 + ((((p << 1) | v_u) ^ (vrow & 7)) << 4));
                uint32_t vh[4];
                ldsm4t(vh, sb + 16384 + vo);
                mma_f16(O[2 * p],     ph, vh);
                mma_f16(O[2 * p + 1], ph, vh + 2);
            }
        }
    }

    l0 += __shfl_xor_sync(0xffffffffu, l0, 1);
    l0 += __shfl_xor_sync(0xffffffffu, l0, 2);
    l1 += __shfl_xor_sync(0xffffffffu, l1, 1);
    l1 += __shfl_xor_sync(0xffffffffu, l1, 2);
    const float i0 = 1.0f / l0, i1 = 1.0f / l1;
    const int row0 = qb + wid * 16 + r, row1 = row0 + 8;
#pragma unroll
    for (int nt = 0; nt < 8; ++nt) {
        int col = h * HDD + 8 * nt + 2 * c;
        size_t idx0 = ((size_t)b * TT + row0) * CC + col;
        size_t idx1 = ((size_t)b * TT + row1) * CC + col;
        *(uint32_t*)&ohi[idx0] = pack2h(O[nt][0] * i0, O[nt][1] * i0);
        *(uint32_t*)&ohi[idx1] = pack2h(O[nt][2] * i1, O[nt][3] * i1);
    }
}

// ---------------- LayerNorm + residual ----------------
__device__ __forceinline__ float block_sum(float v, float* red) {
    const int lane = threadIdx.x & 31, w = threadIdx.x >> 5;
#pragma unroll
    for (int o = 16; o; o >>= 1) v += __shfl_xor_sync(0xffffffffu, v, o);
    if (lane == 0) red[w] = v;
    __syncthreads();
    if (w == 0) {
        float s = (lane < 8) ? red[lane] : 0.0f;
#pragma unroll
        for (int o = 4; o; o >>= 1) s += __shfl_xor_sync(0xffffffffu, s, o);
        if (lane == 0) red[0] = s;
    }
    __syncthreads();
    float rr = red[0];
    __syncthreads();
    return rr;
}

template<bool SPLIT>
__global__ void __launch_bounds__(256)
ln_res_kernel(const float* __restrict__ res, const float* __restrict__ y,
              const float* __restrict__ g, const float* __restrict__ be,
              float* __restrict__ out, __half* __restrict__ ohi)
{
    __shared__ float red[8];
    const int row = blockIdx.x;
    const int t = threadIdx.x;
    const float* yr = y + (size_t)row * CC;

    float v[4];
    float s = 0.0f;
#pragma unroll
    for (int i = 0; i < 4; ++i) { v[i] = yr[t + i * 256]; s += v[i]; }
    const float mean = block_sum(s, red) * (1.0f / CC);

    float sq = 0.0f;
#pragma unroll
    for (int i = 0; i < 4; ++i) { float d = v[i] - mean; sq += d * d; }
    const float var = block_sum(sq, red) * (1.0f / CC);
    const float rstd = rsqrtf(var + 1e-5f);

    const float* rr = res + (size_t)row * CC;
    float* orow = out + (size_t)row * CC;
#pragma unroll
    for (int i = 0; i < 4; ++i) {
        int cix = t + i * 256;
        float o = rr[cix] + (v[i] - mean) * rstd * g[cix] + be[cix];
        orow[cix] = o;
        if (SPLIT) ohi[(size_t)row * CC + cix] = __float2half_rn(o);
    }
}

// ---------------- launch ----------------
extern "C" void kernel_launch(void* const* d_in, const int* in_sizes, int n_in,
                              void* d_out, int out_size)
{
    const float* x      = (const float*)d_in[0];
    const float* w_attn = (const float*)d_in[1];
    const float* b_attn = (const float*)d_in[2];
    const float* wa1    = (const float*)d_in[3];
    const float* ba1    = (const float*)d_in[4];
    const float* wa2    = (const float*)d_in[5];
    const float* ba2    = (const float*)d_in[6];
    const float* g1     = (const float*)d_in[7];
    const float* be1    = (const float*)d_in[8];
    const float* wf1    = (const float*)d_in[9];
    const float* bf1    = (const float*)d_in[10];
    const float* wf2    = (const float*)d_in[11];
    const float* bf2    = (const float*)d_in[12];
    const float* g2     = (const float*)d_in[13];
    const float* be2    = (const float*)d_in[14];
    float* out = (float*)d_out;

    float *x1, *y;
    cudaGetSymbolAddress((void**)&x1, g_x1);
    cudaGetSymbolAddress((void**)&y,  g_y);

    __half *wqkv_hi, *wa1_hi, *wa2_hi, *wf1_hi, *wf2_hi, *ahi, *hhi, *qkvh;
    cudaGetSymbolAddress((void**)&wqkv_hi, g_wqkv_hi);
    cudaGetSymbolAddress((void**)&wa1_hi,  g_wa1_hi);
    cudaGetSymbolAddress((void**)&wa2_hi,  g_wa2_hi);
    cudaGetSymbolAddress((void**)&wf1_hi,  g_wf1_hi);
    cudaGetSymbolAddress((void**)&wf2_hi,  g_wf2_hi);
    cudaGetSymbolAddress((void**)&ahi,     g_ahi);
    cudaGetSymbolAddress((void**)&hhi,     g_hhi);
    cudaGetSymbolAddress((void**)&qkvh,    g_qkvh);

    cudaFuncSetAttribute(attn_mma_kernel, cudaFuncAttributeMaxDynamicSharedMemorySize, ASMEM);
    cudaFuncSetAttribute(gemm_mma_kernel<0>, cudaFuncAttributeMaxDynamicSharedMemorySize, GS1);
    cudaFuncSetAttribute(gemm_mma_kernel<1>, cudaFuncAttributeMaxDynamicSharedMemorySize, GS1);
    cudaFuncSetAttribute(gemm_mma_kernel<2>, cudaFuncAttributeMaxDynamicSharedMemorySize, GS1);

    // all conversions (5 weights + x) in one launch
    cvt_all_kernel<<<CVT_BLOCKS, 256>>>(
        w_attn, wqkv_hi,
        wa1, wa1_hi,
        wa2, wa2_hi,
        wf1, wf1_hi,
        wf2, wf2_hi,
        x, ahi);

    // 1) qkv = x @ w_attn + b_attn
    gemm_mma_kernel<2><<<dim3(C3 / 128, MTOK / 128), 256, GS1>>>(
        ahi, wqkv_hi, b_attn, nullptr, qkvh, C3, CC);
    // 2) attention
    attn_mma_kernel<<<dim3(TT / 64, NHH, BB), 128, ASMEM>>>(qkvh, ahi);
    // 3) h = gelu(att @ wa1 + ba1)
    gemm_mma_kernel<1><<<dim3(C4 / 128, MTOK / 128), 256, GS1>>>(
        ahi, wa1_hi, ba1, nullptr, hhi, C4, CC);
    // 4) y = h @ wa2 + ba2
    gemm_mma_kernel<0><<<dim3(CC / 128, MTOK / 128), 256, GS1>>>(
        hhi, wa2_hi, ba2, y, nullptr, CC, C4);
    // 5) x1 = x + ln(y); emit fp16 x1
    ln_res_kernel<true><<<MTOK, 256>>>(x, y, g1, be1, x1, ahi);
    // 6) h = gelu(x1 @ wf1 + bf1)
    gemm_mma_kernel<1><<<dim3(C4 / 128, MTOK / 128), 256, GS1>>>(
        ahi, wf1_hi, bf1, nullptr, hhi, C4, CC);
    // 7) y = h @ wf2 + bf2
    gemm_mma_kernel<0><<<dim3(CC / 128, MTOK / 128), 256, GS1>>>(
        hhi, wf2_hi, bf2, y, nullptr, CC, C4);
    // 8) out = x1 + ln(y)
    ln_res_kernel<false><<<MTOK, 256>>>(x1, y, g2, be2, out, nullptr);
}